// round 2
// baseline (speedup 1.0000x reference)
#include <cuda_runtime.h>

#define NROWS  32768      // B*Q*W = 16*8*256
#define DIM    256
#define KCODES 1024
#define NQV    8          // NQ stages

// ---- scratch (static device globals: allocation-free rule) ----
__device__ float  g_res[NROWS * DIM];        // 32 MB residual
__device__ float  g_rnorm[NROWS];            // per-row ||residual||^2 (current stage)
__device__ float  g_cnorm[NQV * KCODES];     // per-code squared norms
__device__ int    g_idx[NROWS];              // argmin per row for current stage
__device__ double g_loss;                    // sum of squared new-residuals across stages

// ============================================================
// init: residual = z ; qtot(out) = 0 ; rnorm = ||z_row||^2 ; loss = 0
// grid: NROWS/4 blocks x 256 threads (4 rows/block, one float4/thread)
// ============================================================
__global__ void init_kernel(const float* __restrict__ z, float* __restrict__ out_q) {
    __shared__ float warpsum[8];
    int tid = threadIdx.x;
    int row = blockIdx.x * 4 + (tid >> 6);
    int d   = (tid & 63) << 2;
    size_t off = (size_t)row * DIM + d;

    float4 v = *(const float4*)&z[off];
    *(float4*)&g_res[off] = v;
    *(float4*)&out_q[off] = make_float4(0.f, 0.f, 0.f, 0.f);

    float ls = v.x * v.x + v.y * v.y + v.z * v.z + v.w * v.w;
    #pragma unroll
    for (int s = 16; s >= 1; s >>= 1) ls += __shfl_xor_sync(0xffffffffu, ls, s);
    if ((tid & 31) == 0) warpsum[tid >> 5] = ls;
    __syncthreads();
    if (tid < 4) g_rnorm[blockIdx.x * 4 + tid] = warpsum[2 * tid] + warpsum[2 * tid + 1];
    if (blockIdx.x == 0 && tid == 0) g_loss = 0.0;
}

// ============================================================
// cnorm: one warp per code, all NQ codebooks at once
// ============================================================
__global__ void cnorm_kernel(const float* __restrict__ cbs) {
    int gw   = (blockIdx.x * blockDim.x + threadIdx.x) >> 5;  // code id 0..8191
    int lane = threadIdx.x & 31;
    const float* c = cbs + (size_t)gw * DIM;
    float s = 0.f;
    #pragma unroll
    for (int d = lane; d < DIM; d += 32) { float v = c[d]; s += v * v; }
    #pragma unroll
    for (int sh = 16; sh >= 1; sh >>= 1) s += __shfl_xor_sync(0xffffffffu, s, sh);
    if (lane == 0) g_cnorm[gw] = s;
}

// ============================================================
// argmin GEMM: 128 rows x all 1024 codes per block, SGEMM tiling
//   acc  = dot(2*res_row, code_k)          (replicates (2.0*flat) @ cb.T)
//   dist = (rnorm - acc) + cnorm           (left-assoc, as reference)
// ============================================================
#define BM  128
#define BN  128
#define BKD 8
#define TM  8
#define TN  8

__global__ __launch_bounds__(256, 2)
void argmin_kernel(const float* __restrict__ cb,      // stage codebook [K][D]
                   float* __restrict__ out_tok,       // d_out + NROWS*DIM
                   int stage)
{
    __shared__ float As[BKD][BM + 4];   // transposed 2*residual tile [d][row]
    __shared__ float Bs[BKD][BN + 4];   // transposed code tile       [d][code]

    const int tid = threadIdx.x;
    const int tx  = tid & 15;          // code-group 0..15
    const int ty  = tid >> 4;          // row-group  0..15
    const int rowBase = blockIdx.x * BM;

    const int lr = tid >> 1;           // 0..127 : row/code for loading
    const int lh = (tid & 1) * 4;      // 0 or 4 : d sub-offset

    const float* __restrict__ res   = g_res;
    const float* __restrict__ cnorm = g_cnorm + (size_t)stage * KCODES;

    float rn[TM];
    #pragma unroll
    for (int i = 0; i < TM; i++) rn[i] = g_rnorm[rowBase + ty * TM + i];

    float bestD[TM];
    int   bestI[TM];
    #pragma unroll
    for (int i = 0; i < TM; i++) { bestD[i] = 3.402823466e38f; bestI[i] = 0; }

    for (int cc = 0; cc < KCODES; cc += BN) {
        float acc[TM][TN];
        #pragma unroll
        for (int i = 0; i < TM; i++)
            #pragma unroll
            for (int j = 0; j < TN; j++) acc[i][j] = 0.f;

        for (int dk = 0; dk < DIM; dk += BKD) {
            __syncthreads();
            float4 av = *(const float4*)&res[(size_t)(rowBase + lr) * DIM + dk + lh];
            float4 bv = *(const float4*)&cb [(size_t)(cc      + lr) * DIM + dk + lh];
            As[lh + 0][lr] = 2.0f * av.x; As[lh + 1][lr] = 2.0f * av.y;
            As[lh + 2][lr] = 2.0f * av.z; As[lh + 3][lr] = 2.0f * av.w;
            Bs[lh + 0][lr] = bv.x; Bs[lh + 1][lr] = bv.y;
            Bs[lh + 2][lr] = bv.z; Bs[lh + 3][lr] = bv.w;
            __syncthreads();

            #pragma unroll
            for (int d = 0; d < BKD; d++) {
                float a[TM], b[TN];
                *(float4*)&a[0] = *(const float4*)&As[d][ty * TM];
                *(float4*)&a[4] = *(const float4*)&As[d][ty * TM + 4];
                *(float4*)&b[0] = *(const float4*)&Bs[d][tx * TN];
                *(float4*)&b[4] = *(const float4*)&Bs[d][tx * TN + 4];
                #pragma unroll
                for (int i = 0; i < TM; i++)
                    #pragma unroll
                    for (int j = 0; j < TN; j++)
                        acc[i][j] += a[i] * b[j];
            }
        }

        // dist = (rn - acc) + cn, matching reference rounding; strict '<' with
        // ascending code order == first-min (jnp.argmin) semantics
        #pragma unroll
        for (int j = 0; j < TN; j++) {
            int code = cc + tx * TN + j;
            float cn = __ldg(&cnorm[code]);
            #pragma unroll
            for (int i = 0; i < TM; i++) {
                float t1 = __fadd_rn(rn[i], -acc[i][j]);
                float dd = __fadd_rn(t1, cn);
                if (dd < bestD[i]) { bestD[i] = dd; bestI[i] = code; }
            }
        }
    }

    // reduce across the 16 tx-threads sharing each row group (ties -> lower index)
    #pragma unroll
    for (int s = 8; s >= 1; s >>= 1) {
        #pragma unroll
        for (int i = 0; i < TM; i++) {
            float od = __shfl_xor_sync(0xffffffffu, bestD[i], s);
            int   oi = __shfl_xor_sync(0xffffffffu, bestI[i], s);
            if (od < bestD[i] || (od == bestD[i] && oi < bestI[i])) {
                bestD[i] = od; bestI[i] = oi;
            }
        }
    }

    if (tx == 0) {
        #pragma unroll
        for (int i = 0; i < TM; i++) {
            int row = rowBase + ty * TM + i;
            g_idx[row] = bestI[i];
            out_tok[(size_t)row * NQV + stage] = (float)bestI[i];
        }
    }
}

// ============================================================
// update: residual -= code ; qtot += code ;
//         rnorm = ||new residual||^2 ; loss += same
// grid: NROWS/4 blocks x 256 threads
// ============================================================
__global__ void update_kernel(const float* __restrict__ cb, float* __restrict__ out_q) {
    __shared__ float warpsum[8];
    int tid = threadIdx.x;
    int row = blockIdx.x * 4 + (tid >> 6);
    int d   = (tid & 63) << 2;
    int idx = g_idx[row];
    size_t off = (size_t)row * DIM + d;

    float4 c = *(const float4*)&cb[(size_t)idx * DIM + d];
    float4 r = *(const float4*)&g_res[off];
    float4 rv = make_float4(r.x - c.x, r.y - c.y, r.z - c.z, r.w - c.w);
    *(float4*)&g_res[off] = rv;

    float4 q = *(const float4*)&out_q[off];
    q.x += c.x; q.y += c.y; q.z += c.z; q.w += c.w;
    *(float4*)&out_q[off] = q;

    float ls = rv.x * rv.x + rv.y * rv.y + rv.z * rv.z + rv.w * rv.w;
    #pragma unroll
    for (int s = 16; s >= 1; s >>= 1) ls += __shfl_xor_sync(0xffffffffu, ls, s);
    if ((tid & 31) == 0) warpsum[tid >> 5] = ls;
    __syncthreads();
    if (tid < 4) g_rnorm[blockIdx.x * 4 + tid] = warpsum[2 * tid] + warpsum[2 * tid + 1];
    if (tid == 0) {
        float t = 0.f;
        #pragma unroll
        for (int w = 0; w < 8; w++) t += warpsum[w];
        atomicAdd(&g_loss, (double)t);
    }
}

// ============================================================
// finalize: quantized = z + (qtot - z) ; write closs scalar
// ============================================================
__global__ void finalize_kernel(const float* __restrict__ z, float* __restrict__ out) {
    int i = blockIdx.x * blockDim.x + threadIdx.x;   // over 2097152 float4
    float4 zv = ((const float4*)z)[i];
    float4 qv = ((const float4*)out)[i];
    qv.x = zv.x + (qv.x - zv.x);
    qv.y = zv.y + (qv.y - zv.y);
    qv.z = zv.z + (qv.z - zv.z);
    qv.w = zv.w + (qv.w - zv.w);
    ((float4*)out)[i] = qv;
    if (i == 0) {
        double closs = 1.25 * g_loss / ((double)NROWS * (double)DIM * (double)NQV);
        out[(size_t)NROWS * DIM + (size_t)NROWS * NQV] = (float)closs;
    }
}

// ============================================================
extern "C" void kernel_launch(void* const* d_in, const int* in_sizes, int n_in,
                              void* d_out, int out_size) {
    const float* z   = (const float*)d_in[0];   // [16,8,256,256] float32
    const float* cbs = (const float*)d_in[1];   // [8,1024,256]   float32
    float* out     = (float*)d_out;
    float* out_tok = out + (size_t)NROWS * DIM;

    init_kernel<<<NROWS / 4, 256>>>(z, out);
    cnorm_kernel<<<(NQV * KCODES * 32) / 256, 256>>>(cbs);

    for (int s = 0; s < NQV; s++) {
        const float* cb = cbs + (size_t)s * KCODES * DIM;
        argmin_kernel<<<NROWS / BM, 256>>>(cb, out_tok, s);
        update_kernel<<<NROWS / 4, 256>>>(cb, out);
    }

    finalize_kernel<<<(NROWS * DIM / 4) / 256, 256>>>(z, out);
}